// round 14
// baseline (speedup 1.0000x reference)
#include <cuda_runtime.h>
#include <cuda_fp16.h>
#include <cstdint>

#define Bn   4096
#define S    1024     // H*W
#define DIN  3072     // H*W*3
#define NOUT 2048     // 2*H*W
#define KITER 20

// ---------------- scratch (device globals; no allocation allowed) ----------
// A and B packed as 8KB tiles: tile = 128 rows x 32 halves, row stride 64B,
// 16B chunk swizzle: c16' = c16 ^ ((row>>1)&3)  -> ldmatrix conflict-free.
__device__ __half  d_pA[Bn * S];        // (Bn/128)*(S/32) tiles
__device__ __half  d_pB[NOUT * S];      // (NOUT/128)*(S/32) tiles
__device__ __half2 d_phi[Bn * S];       // (r,p) per cell, fp16x2
__device__ int     d_agent[Bn];
__device__ int     d_goal[Bn];
__device__ float   d_aval[Bn];
__device__ float   d_gval[Bn];

__device__ __forceinline__ int packed_off(int row, int k) {   // row 0..127, k 0..31
    int c16 = ((k >> 3) ^ ((row >> 1) & 3));
    return row * 32 + c16 * 8 + (k & 7);
}

// ---------------- kernel 0: pack walls + argmax of agent/goal channels -----
__global__ void prep_kernel(const float* __restrict__ obs) {
    int b = blockIdx.x;
    const float* row = obs + (size_t)b * DIN;
    __shared__ unsigned long long ka, kg;
    if (threadIdx.x == 0) { ka = 0ull; kg = 0ull; }
    __syncthreads();
    unsigned long long la = 0ull, lg = 0ull;
    __half* tbase = d_pA + (size_t)((b >> 7) * 32) * 4096;
    const int prow = b & 127;
    for (int s = threadIdx.x; s < S; s += blockDim.x) {
        float w = row[3 * s + 0];
        float a = row[3 * s + 1];
        float g = row[3 * s + 2];
        tbase[(size_t)(s >> 5) * 4096 + packed_off(prow, s & 31)] = __float2half_rn(w);
        unsigned long long keya =
            ((unsigned long long)__float_as_uint(a) << 32) | (unsigned)(0xFFFFFFFFu - s);
        unsigned long long keyg =
            ((unsigned long long)__float_as_uint(g) << 32) | (unsigned)(0xFFFFFFFFu - s);
        if (keya > la) la = keya;
        if (keyg > lg) lg = keyg;
    }
    atomicMax(&ka, la);
    atomicMax(&kg, lg);
    __syncthreads();
    if (threadIdx.x == 0) {
        unsigned long long va = ka, vg = kg;
        d_agent[b] = (int)(0xFFFFFFFFu - (unsigned)(va & 0xFFFFFFFFull));
        d_aval[b]  = __uint_as_float((unsigned)(va >> 32));
        d_goal[b]  = (int)(0xFFFFFFFFu - (unsigned)(vg & 0xFFFFFFFFull));
        d_gval[b]  = __uint_as_float((unsigned)(vg >> 32));
    }
}

// ------ kernel 1: transpose dense weight rows -> packed B tiles (fp16) -----
__global__ void wtrans_kernel(const float* __restrict__ Phi_w) {
    __shared__ float t[32][33];
    const int k0 = blockIdx.x * 32, n0 = blockIdx.y * 32;
    const int tx = threadIdx.x & 31, ty = threadIdx.x >> 5;   // 256 thr: ty 0..7
    #pragma unroll
    for (int i = ty; i < 32; i += 8)
        t[i][tx] = Phi_w[(size_t)(3 * (k0 + i)) * NOUT + n0 + tx];
    __syncthreads();
    #pragma unroll
    for (int i = ty; i < 32; i += 8) {
        int n = n0 + i, k = k0 + tx;
        d_pB[(size_t)((n >> 7) * 32 + (k >> 5)) * 4096 + packed_off(n & 127, k & 31)]
            = __float2half_rn(t[tx][i]);
    }
}

// -------- kernel 2: fp16 GEMM, BK=64 bulk-copy pipeline + ldmatrix ---------
#define BM 128
#define BN 128
#define NSTG 16                 // K stages of 64
#define STAGE_BYTES 32768       // A 16KB + B 16KB
#define SMEM_BUFS 3
#define GEMM_SMEM (1024 + SMEM_BUFS * STAGE_BYTES)

__device__ __forceinline__ void mma_f16(float* c, const uint32_t* a, const uint32_t* b) {
    asm volatile(
        "mma.sync.aligned.m16n8k16.row.col.f32.f16.f16.f32 "
        "{%0,%1,%2,%3}, {%4,%5,%6,%7}, {%8,%9}, {%0,%1,%2,%3};\n"
        : "+f"(c[0]), "+f"(c[1]), "+f"(c[2]), "+f"(c[3])
        : "r"(a[0]), "r"(a[1]), "r"(a[2]), "r"(a[3]), "r"(b[0]), "r"(b[1]));
}

__device__ __forceinline__ void ldsm4(uint32_t& r0, uint32_t& r1, uint32_t& r2,
                                      uint32_t& r3, uint32_t addr) {
    asm volatile("ldmatrix.sync.aligned.m8n8.x4.shared.b16 {%0,%1,%2,%3}, [%4];"
                 : "=r"(r0), "=r"(r1), "=r"(r2), "=r"(r3) : "r"(addr));
}

__device__ __forceinline__ void mbar_wait(uint32_t mbar, uint32_t parity) {
    uint32_t done;
    asm volatile(
        "{\n .reg .pred p;\n"
        " mbarrier.try_wait.parity.acquire.cta.shared::cta.b64 p, [%1], %2;\n"
        " selp.b32 %0, 1, 0, p;\n}"
        : "=r"(done) : "r"(mbar), "r"(parity) : "memory");
    if (!done) {
        asm volatile(
            "{\n .reg .pred P1;\n"
            "WL%=:\n"
            " mbarrier.try_wait.parity.acquire.cta.shared::cta.b64 P1, [%0], %1, 0x989680;\n"
            " @P1 bra.uni WD%=;\n"
            " bra.uni WL%=;\n"
            "WD%=:\n}"
            :: "r"(mbar), "r"(parity) : "memory");
    }
}

__device__ __forceinline__ void bulkcp(uint32_t dst, const void* src, uint32_t bytes,
                                       uint32_t mbar) {
    asm volatile(
        "cp.async.bulk.shared::cta.global.mbarrier::complete_tx::bytes "
        "[%0], [%1], %2, [%3];"
        :: "r"(dst), "l"(src), "r"(bytes), "r"(mbar) : "memory");
}

__global__ __launch_bounds__(256, 2) void gemm_kernel(
    const float* __restrict__ Phi_w, const float* __restrict__ Phi_b)
{
    extern __shared__ __align__(1024) char smem[];
    const uint32_t sb = (uint32_t)__cvta_generic_to_shared(smem);

    const int tid  = threadIdx.x;
    const int warp = tid >> 5;
    const int lane = tid & 31;
    const int wm   = warp >> 2;   // 0..1 -> 64 rows
    const int wn   = warp & 3;    // 0..3 -> 32 cols
    const int bm   = blockIdx.y * BM;
    const int bn   = blockIdx.x * BN;

    const __half* tA = d_pA + (size_t)(blockIdx.y * 32) * 4096;
    const __half* tB = d_pB + (size_t)(blockIdx.x * 32) * 4096;

    if (tid == 0) {
        #pragma unroll
        for (int i = 0; i < SMEM_BUFS; i++)
            asm volatile("mbarrier.init.shared.b64 [%0], 1;" :: "r"(sb + i * 8) : "memory");
        asm volatile("fence.proxy.async.shared::cta;" ::: "memory");
    }
    __syncthreads();

#define ISSUE(ST)                                                                     \
    do {                                                                              \
        const int _b = (ST) % SMEM_BUFS;                                              \
        const uint32_t _mb = sb + _b * 8;                                             \
        asm volatile("mbarrier.arrive.expect_tx.shared.b64 _, [%0], %1;"              \
                     :: "r"(_mb), "r"((uint32_t)STAGE_BYTES) : "memory");             \
        bulkcp(sb + 1024 + _b * STAGE_BYTES,         tA + (size_t)(ST) * 8192,        \
               16384u, _mb);                                                          \
        bulkcp(sb + 1024 + _b * STAGE_BYTES + 16384, tB + (size_t)(ST) * 8192,        \
               16384u, _mb);                                                          \
    } while (0)

    if (tid == 0) { ISSUE(0); ISSUE(1); }

    float accf[4][4][4];
    #pragma unroll
    for (int i = 0; i < 4; i++)
        #pragma unroll
        for (int j = 0; j < 4; j++)
            #pragma unroll
            for (int k = 0; k < 4; k++) accf[i][j][k] = 0.f;

    #pragma unroll 1
    for (int s = 0; s < NSTG; s++) {
        const int buf = s % SMEM_BUFS;
        mbar_wait(sb + buf * 8, (uint32_t)((s / SMEM_BUFS) & 1));

        const uint32_t aBase = sb + 1024 + buf * STAGE_BYTES;
        const uint32_t bBase = aBase + 16384;

        #pragma unroll
        for (int kk = 0; kk < 4; kk++) {          // four k16 steps within BK=64
            uint32_t afr[4][4];
            uint32_t bfr[4][2];
            const uint32_t tOff = (kk >> 1) * 8192;      // which packed tile
            const int cc = ((kk & 1) << 1) + (lane >> 4);
            #pragma unroll
            for (int mt = 0; mt < 4; mt++) {
                const int row = wm * 64 + mt * 16 + (lane & 15);
                uint32_t addr = aBase + tOff + row * 64 + ((cc ^ ((row >> 1) & 3)) << 4);
                ldsm4(afr[mt][0], afr[mt][1], afr[mt][2], afr[mt][3], addr);
            }
            #pragma unroll
            for (int np = 0; np < 2; np++) {
                const int row = wn * 32 + np * 16 + (lane & 15);
                uint32_t addr = bBase + tOff + row * 64 + ((cc ^ ((row >> 1) & 3)) << 4);
                ldsm4(bfr[2 * np][0], bfr[2 * np + 1][0],
                      bfr[2 * np][1], bfr[2 * np + 1][1], addr);
            }
            #pragma unroll
            for (int mt = 0; mt < 4; mt++)
                #pragma unroll
                for (int nt = 0; nt < 4; nt++)
                    mma_f16(accf[mt][nt], afr[mt], bfr[nt]);
        }
        __syncthreads();
        if (s + 2 < NSTG && tid == 0) ISSUE(s + 2);
    }
#undef ISSUE

    // ---- epilogue: + agent/goal gathers + bias, sigmoid, store half2(r,p) --
    #pragma unroll
    for (int mt = 0; mt < 4; mt++) {
        #pragma unroll
        for (int rsub = 0; rsub < 2; rsub++) {
            const int gr = bm + wm * 64 + mt * 16 + (lane >> 2) + rsub * 8;
            const int ai = d_agent[gr];
            const int gi = d_goal[gr];
            const float av = d_aval[gr];
            const float gv = d_gval[gr];
            const float* arow = Phi_w + (size_t)(3 * ai + 1) * NOUT;
            const float* grow = Phi_w + (size_t)(3 * gi + 2) * NOUT;
            #pragma unroll
            for (int nt = 0; nt < 4; nt++) {
                const int gn = bn + wn * 32 + nt * 8 + (lane & 3) * 2;
                float x0 = accf[mt][nt][rsub * 2 + 0]
                         + av * arow[gn] + gv * grow[gn] + Phi_b[gn];
                float x1 = accf[mt][nt][rsub * 2 + 1]
                         + av * arow[gn + 1] + gv * grow[gn + 1] + Phi_b[gn + 1];
                float r = 1.f / (1.f + __expf(-x0));
                float p = 1.f / (1.f + __expf(-x1));
                d_phi[(size_t)gr * S + (gn >> 1)] = __floats2half2_rn(r, p);
            }
        }
    }
}

// --- kernel 3: vprop fp16x2, ONE sample/warp, rows (i,i+16) packed ---------
__global__ __launch_bounds__(128) void vprop_kernel(
    const float* __restrict__ obs,
    const float* __restrict__ L1w, const float* __restrict__ L1b,
    const float* __restrict__ L2w, const float* __restrict__ L2b,
    float* __restrict__ out)
{
    const int warp = threadIdx.x >> 5;
    const int lane = threadIdx.x & 31;
    const int b = blockIdx.x * 4 + warp;
    const unsigned FULL = 0xFFFFFFFFu;

    __shared__ __half Vsh[4][S];                     // 8KB: final V per warp
    __shared__ float ssel[4][36];
    __shared__ float shh[4][16];

    // V[i] = (row i, row i+16) of this sample, one column per lane
    __half2 V[16], p2[16], a2[16];
    const __half2* phi = d_phi + (size_t)b * S;
    #pragma unroll
    for (int i = 0; i < 16; i++) {
        uint32_t u0 = *(const uint32_t*)&phi[i * 32 + lane];          // (r,p) row i
        uint32_t u1 = *(const uint32_t*)&phi[(i + 16) * 32 + lane];   // row i+16
        uint32_t Vu = __byte_perm(u0, u1, 0x5410);                    // (r_i, r_i16)
        uint32_t Pu = __byte_perm(u0, u1, 0x7632);                    // (p_i, p_i16)
        V[i]  = *(__half2*)&Vu;
        p2[i] = *(__half2*)&Pu;
        a2[i] = __hsub2(V[i], __hmul2(V[i], p2[i]));                  // r*(1-p)
    }

    // 20 Jacobi iterations. Out-of-grid neighbor := self is a no-op (V>=r, p<1).
    // Seam rows 15/16 cross the lo/hi halves: 2 PRMTs per iteration.
    #pragma unroll 1
    for (int it = 0; it < KITER; it++) {
        const uint32_t v0u  = *(uint32_t*)&V[0];
        const uint32_t v15u = *(uint32_t*)&V[15];
        // prev for i=0: rows (-1->self row0, 15) = (lo V0, lo V15), all old
        uint32_t pv = __byte_perm(v0u, v15u, 0x5410);
        __half2 prev = *(__half2*)&pv;
        #pragma unroll
        for (int i = 0; i < 16; i++) {
            __half2 cur = V[i];
            __half2 dn;
            if (i < 15) dn = V[i + 1];                    // rows (i+1, i+17), old
            else {
                // rows (16, 32->self row31) = (hi V0old, hi V15)
                uint32_t d = __byte_perm(v0u, *(uint32_t*)&cur, 0x7632);
                dn = *(__half2*)&d;
            }
            uint32_t cu = *(uint32_t*)&cur;
            uint32_t lfu = __shfl_up_sync(FULL, cu, 1);   // lane0 -> self
            uint32_t rtu = __shfl_down_sync(FULL, cu, 1); // lane31 -> self
            __half2 lf = *(__half2*)&lfu;
            __half2 rt = *(__half2*)&rtu;
            __half2 nbr = __hmax2(__hmax2(prev, dn), __hmax2(lf, rt));
            V[i] = __hmax2(cur, __hfma2(p2[i], nbr, a2[i]));
            prev = cur;
        }
    }

    // publish final V (lo -> row i, hi -> row i+16)
    #pragma unroll
    for (int i = 0; i < 16; i++) {
        Vsh[warp][i * 32 + lane]        = __low2half(V[i]);
        Vsh[warp][(i + 16) * 32 + lane] = __high2half(V[i]);
    }
    __syncwarp();

    // ---- head: 3x3 gather around agent + 36->16->4 MLP --------------------
    const int ai = d_agent[b];
    const int gi = d_goal[b];
    const int pi = ai >> 5, pj = ai & 31;
    if (lane < 9) {
        const int di = lane / 3, dj = lane - di * 3;
        const int ii = pi + di - 1, jj = pj + dj - 1;
        const bool inb = (ii >= 0) && (ii < 32) && (jj >= 0) && (jj < 32);
        const int sp = ii * 32 + jj;
        ssel[warp][lane * 4 + 0] = inb ? obs[(size_t)b * DIN + sp * 3 + 0] : 0.f;
        ssel[warp][lane * 4 + 1] = (lane == 4) ? 1.f : 0.f;
        ssel[warp][lane * 4 + 2] = (inb && sp == gi) ? 1.f : 0.f;
        ssel[warp][lane * 4 + 3] = inb ? __half2float(Vsh[warp][sp]) : 0.f;
    }
    __syncwarp();
    if (lane < 16) {
        float h = L1b[lane];
        #pragma unroll
        for (int f = 0; f < 36; f++) h = fmaf(ssel[warp][f], L1w[f * 16 + lane], h);
        shh[warp][lane] = fmaxf(h, 0.f);
    }
    __syncwarp();
    if (lane < 4) {
        float o = L2b[lane];
        #pragma unroll
        for (int k = 0; k < 16; k++) o = fmaf(shh[warp][k], L2w[k * 4 + lane], o);
        out[(size_t)b * 4 + lane] = o;
    }
}

// ---------------------------------------------------------------------------
extern "C" void kernel_launch(void* const* d_in, const int* in_sizes, int n_in,
                              void* d_out, int out_size) {
    const float* obs   = (const float*)d_in[0];
    const float* Phi_w = (const float*)d_in[1];
    const float* Phi_b = (const float*)d_in[2];
    const float* L1w   = (const float*)d_in[3];
    const float* L1b   = (const float*)d_in[4];
    const float* L2w   = (const float*)d_in[5];
    const float* L2b   = (const float*)d_in[6];
    float* out = (float*)d_out;

    prep_kernel<<<Bn, 256>>>(obs);
    wtrans_kernel<<<dim3(32, 64), 256>>>(Phi_w);
    cudaFuncSetAttribute(gemm_kernel,
                         cudaFuncAttributeMaxDynamicSharedMemorySize, GEMM_SMEM);
    dim3 g(NOUT / BN, Bn / BM);
    gemm_kernel<<<g, 256, GEMM_SMEM>>>(Phi_w, Phi_b);
    vprop_kernel<<<Bn / 4, 128>>>(obs, L1w, L1b, L2w, L2b, out);
}

// round 16
// speedup vs baseline: 1.5099x; 1.5099x over previous
#include <cuda_runtime.h>
#include <cuda_fp16.h>
#include <cstdint>

#define Bn   4096
#define S    1024     // H*W
#define DIN  3072     // H*W*3
#define NOUT 2048     // 2*H*W
#define KITER 20

// ---------------- scratch (device globals; no allocation allowed) ----------
// A and B packed as 8KB tiles: tile = 128 rows x 32 halves, row stride 64B,
// 16B chunk swizzle: c16' = c16 ^ ((row>>1)&3)  -> ldmatrix conflict-free.
__device__ __half  d_pA[Bn * S];        // (Bn/128)*(S/32) tiles
__device__ __half  d_pB[NOUT * S];      // (NOUT/128)*(S/32) tiles
__device__ __half2 d_phi[Bn * S];       // (r,p) per cell, fp16x2
__device__ int     d_agent[Bn];
__device__ int     d_goal[Bn];
__device__ float   d_aval[Bn];
__device__ float   d_gval[Bn];

__device__ __forceinline__ int packed_off(int row, int k) {   // row 0..127, k 0..31
    int c16 = ((k >> 3) ^ ((row >> 1) & 3));
    return row * 32 + c16 * 8 + (k & 7);
}

// -- kernel 0: fused {pack walls + argmax} (blocks 0..4095) and
//              {weight transpose -> packed B tiles} (blocks 4096..6143) -----
__global__ __launch_bounds__(256) void prep_fused_kernel(
    const float* __restrict__ obs, const float* __restrict__ Phi_w)
{
    __shared__ union {
        unsigned long long keys[2];
        float t[32][33];
    } sh;

    if (blockIdx.x < Bn) {
        const int b = blockIdx.x;
        const float* row = obs + (size_t)b * DIN;
        if (threadIdx.x == 0) { sh.keys[0] = 0ull; sh.keys[1] = 0ull; }
        __syncthreads();
        unsigned long long la = 0ull, lg = 0ull;
        __half* tbase = d_pA + (size_t)((b >> 7) * 32) * 4096;
        const int prow = b & 127;
        for (int s = threadIdx.x; s < S; s += blockDim.x) {
            float w = row[3 * s + 0];
            float a = row[3 * s + 1];
            float g = row[3 * s + 2];
            tbase[(size_t)(s >> 5) * 4096 + packed_off(prow, s & 31)] = __float2half_rn(w);
            unsigned long long keya =
                ((unsigned long long)__float_as_uint(a) << 32) | (unsigned)(0xFFFFFFFFu - s);
            unsigned long long keyg =
                ((unsigned long long)__float_as_uint(g) << 32) | (unsigned)(0xFFFFFFFFu - s);
            if (keya > la) la = keya;
            if (keyg > lg) lg = keyg;
        }
        atomicMax(&sh.keys[0], la);
        atomicMax(&sh.keys[1], lg);
        __syncthreads();
        if (threadIdx.x == 0) {
            unsigned long long va = sh.keys[0], vg = sh.keys[1];
            d_agent[b] = (int)(0xFFFFFFFFu - (unsigned)(va & 0xFFFFFFFFull));
            d_aval[b]  = __uint_as_float((unsigned)(va >> 32));
            d_goal[b]  = (int)(0xFFFFFFFFu - (unsigned)(vg & 0xFFFFFFFFull));
            d_gval[b]  = __uint_as_float((unsigned)(vg >> 32));
        }
    } else {
        const int wb = blockIdx.x - Bn;           // 0..2047
        const int k0 = (wb & 31) * 32, n0 = (wb >> 5) * 32;
        const int tx = threadIdx.x & 31, ty = threadIdx.x >> 5;   // ty 0..7
        #pragma unroll
        for (int i = ty; i < 32; i += 8)
            sh.t[i][tx] = Phi_w[(size_t)(3 * (k0 + i)) * NOUT + n0 + tx];
        __syncthreads();
        #pragma unroll
        for (int i = ty; i < 32; i += 8) {
            int n = n0 + i, k = k0 + tx;
            d_pB[(size_t)((n >> 7) * 32 + (k >> 5)) * 4096 + packed_off(n & 127, k & 31)]
                = __float2half_rn(sh.t[tx][i]);
        }
    }
}

// -------- kernel 2: fp16 GEMM, BK=64 bulk-copy pipeline + ldmatrix ---------
#define BM 128
#define BN 128
#define NSTG 16                 // K stages of 64
#define STAGE_BYTES 32768       // A 16KB + B 16KB
#define SMEM_BUFS 3
#define GEMM_SMEM (1024 + SMEM_BUFS * STAGE_BYTES)

__device__ __forceinline__ void mma_f16(float* c, const uint32_t* a, const uint32_t* b) {
    asm volatile(
        "mma.sync.aligned.m16n8k16.row.col.f32.f16.f16.f32 "
        "{%0,%1,%2,%3}, {%4,%5,%6,%7}, {%8,%9}, {%0,%1,%2,%3};\n"
        : "+f"(c[0]), "+f"(c[1]), "+f"(c[2]), "+f"(c[3])
        : "r"(a[0]), "r"(a[1]), "r"(a[2]), "r"(a[3]), "r"(b[0]), "r"(b[1]));
}

__device__ __forceinline__ void ldsm4(uint32_t& r0, uint32_t& r1, uint32_t& r2,
                                      uint32_t& r3, uint32_t addr) {
    asm volatile("ldmatrix.sync.aligned.m8n8.x4.shared.b16 {%0,%1,%2,%3}, [%4];"
                 : "=r"(r0), "=r"(r1), "=r"(r2), "=r"(r3) : "r"(addr));
}

__device__ __forceinline__ void mbar_wait(uint32_t mbar, uint32_t parity) {
    uint32_t done;
    asm volatile(
        "{\n .reg .pred p;\n"
        " mbarrier.try_wait.parity.acquire.cta.shared::cta.b64 p, [%1], %2;\n"
        " selp.b32 %0, 1, 0, p;\n}"
        : "=r"(done) : "r"(mbar), "r"(parity) : "memory");
    if (!done) {
        asm volatile(
            "{\n .reg .pred P1;\n"
            "WL%=:\n"
            " mbarrier.try_wait.parity.acquire.cta.shared::cta.b64 P1, [%0], %1, 0x989680;\n"
            " @P1 bra.uni WD%=;\n"
            " bra.uni WL%=;\n"
            "WD%=:\n}"
            :: "r"(mbar), "r"(parity) : "memory");
    }
}

__device__ __forceinline__ void bulkcp(uint32_t dst, const void* src, uint32_t bytes,
                                       uint32_t mbar) {
    asm volatile(
        "cp.async.bulk.shared::cta.global.mbarrier::complete_tx::bytes "
        "[%0], [%1], %2, [%3];"
        :: "r"(dst), "l"(src), "r"(bytes), "r"(mbar) : "memory");
}

__global__ __launch_bounds__(256, 2) void gemm_kernel(
    const float* __restrict__ Phi_w, const float* __restrict__ Phi_b)
{
    extern __shared__ __align__(1024) char smem[];
    const uint32_t sb = (uint32_t)__cvta_generic_to_shared(smem);

    const int tid  = threadIdx.x;
    const int warp = tid >> 5;
    const int lane = tid & 31;
    const int wm   = warp >> 2;   // 0..1 -> 64 rows
    const int wn   = warp & 3;    // 0..3 -> 32 cols
    const int bm   = blockIdx.y * BM;
    const int bn   = blockIdx.x * BN;

    const __half* tA = d_pA + (size_t)(blockIdx.y * 32) * 4096;
    const __half* tB = d_pB + (size_t)(blockIdx.x * 32) * 4096;

    if (tid == 0) {
        #pragma unroll
        for (int i = 0; i < SMEM_BUFS; i++)
            asm volatile("mbarrier.init.shared.b64 [%0], 1;" :: "r"(sb + i * 8) : "memory");
        asm volatile("fence.proxy.async.shared::cta;" ::: "memory");
    }
    __syncthreads();

#define ISSUE(ST)                                                                     \
    do {                                                                              \
        const int _b = (ST) % SMEM_BUFS;                                              \
        const uint32_t _mb = sb + _b * 8;                                             \
        asm volatile("mbarrier.arrive.expect_tx.shared.b64 _, [%0], %1;"              \
                     :: "r"(_mb), "r"((uint32_t)STAGE_BYTES) : "memory");             \
        bulkcp(sb + 1024 + _b * STAGE_BYTES,         tA + (size_t)(ST) * 8192,        \
               16384u, _mb);                                                          \
        bulkcp(sb + 1024 + _b * STAGE_BYTES + 16384, tB + (size_t)(ST) * 8192,        \
               16384u, _mb);                                                          \
    } while (0)

    if (tid == 0) { ISSUE(0); ISSUE(1); }

    float accf[4][4][4];
    #pragma unroll
    for (int i = 0; i < 4; i++)
        #pragma unroll
        for (int j = 0; j < 4; j++)
            #pragma unroll
            for (int k = 0; k < 4; k++) accf[i][j][k] = 0.f;

    #pragma unroll 1
    for (int s = 0; s < NSTG; s++) {
        const int buf = s % SMEM_BUFS;
        mbar_wait(sb + buf * 8, (uint32_t)((s / SMEM_BUFS) & 1));

        const uint32_t aBase = sb + 1024 + buf * STAGE_BYTES;
        const uint32_t bBase = aBase + 16384;

        #pragma unroll
        for (int kk = 0; kk < 4; kk++) {          // four k16 steps within BK=64
            uint32_t afr[4][4];
            uint32_t bfr[4][2];
            const uint32_t tOff = (kk >> 1) * 8192;      // which packed tile
            const int cc = ((kk & 1) << 1) + (lane >> 4);
            #pragma unroll
            for (int mt = 0; mt < 4; mt++) {
                const int row = wm * 64 + mt * 16 + (lane & 15);
                uint32_t addr = aBase + tOff + row * 64 + ((cc ^ ((row >> 1) & 3)) << 4);
                ldsm4(afr[mt][0], afr[mt][1], afr[mt][2], afr[mt][3], addr);
            }
            #pragma unroll
            for (int np = 0; np < 2; np++) {
                const int row = wn * 32 + np * 16 + (lane & 15);
                uint32_t addr = bBase + tOff + row * 64 + ((cc ^ ((row >> 1) & 3)) << 4);
                ldsm4(bfr[2 * np][0], bfr[2 * np + 1][0],
                      bfr[2 * np][1], bfr[2 * np + 1][1], addr);
            }
            #pragma unroll
            for (int mt = 0; mt < 4; mt++)
                #pragma unroll
                for (int nt = 0; nt < 4; nt++)
                    mma_f16(accf[mt][nt], afr[mt], bfr[nt]);
        }
        __syncthreads();
        if (s + 2 < NSTG && tid == 0) ISSUE(s + 2);
    }
#undef ISSUE

    // ---- epilogue: + agent/goal gathers + bias, sigmoid, store half2(r,p) --
    #pragma unroll
    for (int mt = 0; mt < 4; mt++) {
        #pragma unroll
        for (int rsub = 0; rsub < 2; rsub++) {
            const int gr = bm + wm * 64 + mt * 16 + (lane >> 2) + rsub * 8;
            const int ai = d_agent[gr];
            const int gi = d_goal[gr];
            const float av = d_aval[gr];
            const float gv = d_gval[gr];
            const float* arow = Phi_w + (size_t)(3 * ai + 1) * NOUT;
            const float* grow = Phi_w + (size_t)(3 * gi + 2) * NOUT;
            #pragma unroll
            for (int nt = 0; nt < 4; nt++) {
                const int gn = bn + wn * 32 + nt * 8 + (lane & 3) * 2;
                float x0 = accf[mt][nt][rsub * 2 + 0]
                         + av * arow[gn] + gv * grow[gn] + Phi_b[gn];
                float x1 = accf[mt][nt][rsub * 2 + 1]
                         + av * arow[gn + 1] + gv * grow[gn + 1] + Phi_b[gn + 1];
                float r = 1.f / (1.f + __expf(-x0));
                float p = 1.f / (1.f + __expf(-x1));
                d_phi[(size_t)gr * S + (gn >> 1)] = __floats2half2_rn(r, p);
            }
        }
    }
}

// ---- kernel 3: vprop fp16x2, TWO samples per warp (lo/hi) + MLP head ------
__global__ __launch_bounds__(128) void vprop_kernel(
    const float* __restrict__ obs,
    const float* __restrict__ L1w, const float* __restrict__ L1b,
    const float* __restrict__ L2w, const float* __restrict__ L2b,
    float* __restrict__ out)
{
    const int warp = threadIdx.x >> 5;
    const int lane = threadIdx.x & 31;
    const int b0 = (blockIdx.x * 4 + warp) * 2;      // sample in lo half
    const int b1 = b0 + 1;                           // sample in hi half
    const unsigned FULL = 0xFFFFFFFFu;

    __shared__ __half2 Vsh[4][S];                    // 16KB: final V per warp
    __shared__ float ssel[4][36];
    __shared__ float shh[4][16];

    __half2 V[32], p2[32], a2[32];
    const __half2* phi0 = d_phi + (size_t)b0 * S;
    const __half2* phi1 = d_phi + (size_t)b1 * S;
    #pragma unroll
    for (int i = 0; i < 32; i++) {
        uint32_t u0 = *(const uint32_t*)&phi0[i * 32 + lane];   // (r0,p0)
        uint32_t u1 = *(const uint32_t*)&phi1[i * 32 + lane];   // (r1,p1)
        uint32_t Vu = __byte_perm(u0, u1, 0x5410);              // (r0,r1)
        uint32_t Pu = __byte_perm(u0, u1, 0x7632);              // (p0,p1)
        V[i]  = *(__half2*)&Vu;
        p2[i] = *(__half2*)&Pu;
        a2[i] = __hsub2(V[i], __hmul2(V[i], p2[i]));            // r*(1-p)
    }

    // 20 Jacobi iterations; out-of-range shfl returns self -> boundary no-op
    #pragma unroll 1
    for (int it = 0; it < KITER; it++) {
        __half2 prev = V[0];
        #pragma unroll
        for (int i = 0; i < 32; i++) {
            __half2 cur = V[i];
            __half2 dn  = (i < 31) ? V[i + 1] : cur;
            uint32_t cu = *(uint32_t*)&cur;
            uint32_t lfu = __shfl_up_sync(FULL, cu, 1);
            uint32_t rtu = __shfl_down_sync(FULL, cu, 1);
            __half2 lf = *(__half2*)&lfu;
            __half2 rt = *(__half2*)&rtu;
            __half2 nbr = __hmax2(__hmax2(prev, dn), __hmax2(lf, rt));
            V[i] = __hmax2(cur, __hfma2(p2[i], nbr, a2[i]));
            prev = cur;
        }
    }

    #pragma unroll
    for (int i = 0; i < 32; i++)
        Vsh[warp][i * 32 + lane] = V[i];
    __syncwarp();

    // ---- heads: two samples sequentially, whole warp participates ---------
    #pragma unroll 1
    for (int sh = 0; sh < 2; sh++) {
        const int b = b0 + sh;
        const int ai = d_agent[b];
        const int gi = d_goal[b];
        const int pi = ai >> 5, pj = ai & 31;
        if (lane < 9) {
            const int di = lane / 3, dj = lane - di * 3;
            const int ii = pi + di - 1, jj = pj + dj - 1;
            const bool inb = (ii >= 0) && (ii < 32) && (jj >= 0) && (jj < 32);
            const int sp = ii * 32 + jj;
            float vv = 0.f;
            if (inb) {
                __half2 h = Vsh[warp][sp];
                vv = sh ? __high2float(h) : __low2float(h);
            }
            ssel[warp][lane * 4 + 0] = inb ? obs[(size_t)b * DIN + sp * 3 + 0] : 0.f;
            ssel[warp][lane * 4 + 1] = (lane == 4) ? 1.f : 0.f;
            ssel[warp][lane * 4 + 2] = (inb && sp == gi) ? 1.f : 0.f;
            ssel[warp][lane * 4 + 3] = vv;
        }
        __syncwarp();
        if (lane < 16) {
            float h = L1b[lane];
            #pragma unroll
            for (int f = 0; f < 36; f++) h = fmaf(ssel[warp][f], L1w[f * 16 + lane], h);
            shh[warp][lane] = fmaxf(h, 0.f);
        }
        __syncwarp();
        if (lane < 4) {
            float o = L2b[lane];
            #pragma unroll
            for (int k = 0; k < 16; k++) o = fmaf(shh[warp][k], L2w[k * 4 + lane], o);
            out[(size_t)b * 4 + lane] = o;
        }
        __syncwarp();
    }
}

// ---------------------------------------------------------------------------
extern "C" void kernel_launch(void* const* d_in, const int* in_sizes, int n_in,
                              void* d_out, int out_size) {
    const float* obs   = (const float*)d_in[0];
    const float* Phi_w = (const float*)d_in[1];
    const float* Phi_b = (const float*)d_in[2];
    const float* L1w   = (const float*)d_in[3];
    const float* L1b   = (const float*)d_in[4];
    const float* L2w   = (const float*)d_in[5];
    const float* L2b   = (const float*)d_in[6];
    float* out = (float*)d_out;

    prep_fused_kernel<<<Bn + 2048, 256>>>(obs, Phi_w);
    cudaFuncSetAttribute(gemm_kernel,
                         cudaFuncAttributeMaxDynamicSharedMemorySize, GEMM_SMEM);
    dim3 g(NOUT / BN, Bn / BM);
    gemm_kernel<<<g, 256, GEMM_SMEM>>>(Phi_w, Phi_b);
    vprop_kernel<<<Bn / 8, 128>>>(obs, L1w, L1b, L2w, L2b, out);
}

// round 17
// speedup vs baseline: 1.5232x; 1.0088x over previous
#include <cuda_runtime.h>
#include <cuda_fp16.h>
#include <cstdint>

#define Bn   4096
#define S    1024     // H*W
#define DIN  3072     // H*W*3
#define NOUT 2048     // 2*H*W
#define KITER 20

// ---------------- scratch (device globals; no allocation allowed) ----------
// A and B packed as 8KB tiles: tile = 128 rows x 32 halves, row stride 64B,
// 16B chunk swizzle: c16' = c16 ^ ((row>>1)&3)  -> ldmatrix conflict-free.
__device__ __half  d_pA[Bn * S];        // (Bn/128)*(S/32) tiles
__device__ __half  d_pB[NOUT * S];      // (NOUT/128)*(S/32) tiles
__device__ __half2 d_phi[Bn * S];       // (r,p) per cell, fp16x2
__device__ int     d_agent[Bn];
__device__ int     d_goal[Bn];
__device__ float   d_aval[Bn];
__device__ float   d_gval[Bn];

__device__ __forceinline__ int packed_off(int row, int k) {   // row 0..127, k 0..31
    int c16 = ((k >> 3) ^ ((row >> 1) & 3));
    return row * 32 + c16 * 8 + (k & 7);
}

// -- kernel 0: fused {pack walls + argmax} (blocks 0..4095, smem-staged) and
//              {weight transpose -> packed B tiles} (blocks 4096..6143) -----
__global__ __launch_bounds__(256) void prep_fused_kernel(
    const float* __restrict__ obs, const float* __restrict__ Phi_w)
{
    __shared__ union {
        struct { float buf[DIN]; unsigned long long keys[2]; } p;
        float t[32][33];
    } sh;

    if (blockIdx.x < Bn) {
        const int b = blockIdx.x;
        const int t = threadIdx.x;
        if (t == 0) { sh.p.keys[0] = 0ull; sh.p.keys[1] = 0ull; }

        // stage obs row (12KB) into smem, fully coalesced
        const float4* src = (const float4*)(obs + (size_t)b * DIN);
        float4* dst = (float4*)sh.p.buf;
        #pragma unroll
        for (int i = 0; i < 3; i++) dst[t + i * 256] = src[t + i * 256];
        __syncthreads();

        // each thread: 4 cells s0..s0+3 -> 3 x LDS.128 (conflict-free)
        const int s0 = 4 * t;
        const float4 c0 = *(const float4*)&sh.p.buf[3 * s0 + 0];  // w0 a0 g0 w1
        const float4 c1 = *(const float4*)&sh.p.buf[3 * s0 + 4];  // a1 g1 w2 a2
        const float4 c2 = *(const float4*)&sh.p.buf[3 * s0 + 8];  // g2 w3 a3 g3
        const float wv[4] = {c0.x, c0.w, c1.z, c2.y};
        const float av[4] = {c0.y, c1.x, c1.w, c2.z};
        const float gv[4] = {c0.z, c1.y, c2.x, c2.w};

        union { __half h[4]; uint2 u; } pk;
        #pragma unroll
        for (int q = 0; q < 4; q++) pk.h[q] = __float2half_rn(wv[q]);
        __half* pdst = d_pA + (size_t)((b >> 7) * 32 + (s0 >> 5)) * 4096
                     + packed_off(b & 127, s0 & 31);
        *(uint2*)pdst = pk.u;

        unsigned long long la = 0ull, lg = 0ull;
        #pragma unroll
        for (int q = 0; q < 4; q++) {
            const int s = s0 + q;
            unsigned long long keya =
                ((unsigned long long)__float_as_uint(av[q]) << 32) | (unsigned)(0xFFFFFFFFu - s);
            unsigned long long keyg =
                ((unsigned long long)__float_as_uint(gv[q]) << 32) | (unsigned)(0xFFFFFFFFu - s);
            if (keya > la) la = keya;
            if (keyg > lg) lg = keyg;
        }
        atomicMax(&sh.p.keys[0], la);
        atomicMax(&sh.p.keys[1], lg);
        __syncthreads();
        if (t == 0) {
            unsigned long long va = sh.p.keys[0], vg = sh.p.keys[1];
            d_agent[b] = (int)(0xFFFFFFFFu - (unsigned)(va & 0xFFFFFFFFull));
            d_aval[b]  = __uint_as_float((unsigned)(va >> 32));
            d_goal[b]  = (int)(0xFFFFFFFFu - (unsigned)(vg & 0xFFFFFFFFull));
            d_gval[b]  = __uint_as_float((unsigned)(vg >> 32));
        }
    } else {
        const int wb = blockIdx.x - Bn;           // 0..2047
        const int k0 = (wb & 31) * 32, n0 = (wb >> 5) * 32;
        const int tx = threadIdx.x & 31, ty = threadIdx.x >> 5;   // ty 0..7
        #pragma unroll
        for (int i = ty; i < 32; i += 8)
            sh.t[i][tx] = Phi_w[(size_t)(3 * (k0 + i)) * NOUT + n0 + tx];
        __syncthreads();
        #pragma unroll
        for (int i = ty; i < 32; i += 8) {
            int n = n0 + i, k = k0 + tx;
            d_pB[(size_t)((n >> 7) * 32 + (k >> 5)) * 4096 + packed_off(n & 127, k & 31)]
                = __float2half_rn(sh.t[tx][i]);
        }
    }
}

// -------- kernel 2: fp16 GEMM, BK=64 bulk-copy pipeline + ldmatrix ---------
#define BM 128
#define BN 128
#define NSTG 16                 // K stages of 64
#define STAGE_BYTES 32768       // A 16KB + B 16KB
#define SMEM_BUFS 3
#define GEMM_SMEM (1024 + SMEM_BUFS * STAGE_BYTES)

__device__ __forceinline__ void mma_f16(float* c, const uint32_t* a, const uint32_t* b) {
    asm volatile(
        "mma.sync.aligned.m16n8k16.row.col.f32.f16.f16.f32 "
        "{%0,%1,%2,%3}, {%4,%5,%6,%7}, {%8,%9}, {%0,%1,%2,%3};\n"
        : "+f"(c[0]), "+f"(c[1]), "+f"(c[2]), "+f"(c[3])
        : "r"(a[0]), "r"(a[1]), "r"(a[2]), "r"(a[3]), "r"(b[0]), "r"(b[1]));
}

__device__ __forceinline__ void ldsm4(uint32_t& r0, uint32_t& r1, uint32_t& r2,
                                      uint32_t& r3, uint32_t addr) {
    asm volatile("ldmatrix.sync.aligned.m8n8.x4.shared.b16 {%0,%1,%2,%3}, [%4];"
                 : "=r"(r0), "=r"(r1), "=r"(r2), "=r"(r3) : "r"(addr));
}

__device__ __forceinline__ void mbar_wait(uint32_t mbar, uint32_t parity) {
    uint32_t done;
    asm volatile(
        "{\n .reg .pred p;\n"
        " mbarrier.try_wait.parity.acquire.cta.shared::cta.b64 p, [%1], %2;\n"
        " selp.b32 %0, 1, 0, p;\n}"
        : "=r"(done) : "r"(mbar), "r"(parity) : "memory");
    if (!done) {
        asm volatile(
            "{\n .reg .pred P1;\n"
            "WL%=:\n"
            " mbarrier.try_wait.parity.acquire.cta.shared::cta.b64 P1, [%0], %1, 0x989680;\n"
            " @P1 bra.uni WD%=;\n"
            " bra.uni WL%=;\n"
            "WD%=:\n}"
            :: "r"(mbar), "r"(parity) : "memory");
    }
}

__device__ __forceinline__ void bulkcp(uint32_t dst, const void* src, uint32_t bytes,
                                       uint32_t mbar) {
    asm volatile(
        "cp.async.bulk.shared::cta.global.mbarrier::complete_tx::bytes "
        "[%0], [%1], %2, [%3];"
        :: "r"(dst), "l"(src), "r"(bytes), "r"(mbar) : "memory");
}

__global__ __launch_bounds__(256, 2) void gemm_kernel(
    const float* __restrict__ Phi_w, const float* __restrict__ Phi_b)
{
    extern __shared__ __align__(1024) char smem[];
    const uint32_t sb = (uint32_t)__cvta_generic_to_shared(smem);

    const int tid  = threadIdx.x;
    const int warp = tid >> 5;
    const int lane = tid & 31;
    const int wm   = warp >> 2;   // 0..1 -> 64 rows
    const int wn   = warp & 3;    // 0..3 -> 32 cols
    const int bm   = blockIdx.y * BM;
    const int bn   = blockIdx.x * BN;

    const __half* tA = d_pA + (size_t)(blockIdx.y * 32) * 4096;
    const __half* tB = d_pB + (size_t)(blockIdx.x * 32) * 4096;

    if (tid == 0) {
        #pragma unroll
        for (int i = 0; i < SMEM_BUFS; i++)
            asm volatile("mbarrier.init.shared.b64 [%0], 1;" :: "r"(sb + i * 8) : "memory");
        asm volatile("fence.proxy.async.shared::cta;" ::: "memory");
    }
    __syncthreads();

#define ISSUE(ST)                                                                     \
    do {                                                                              \
        const int _b = (ST) % SMEM_BUFS;                                              \
        const uint32_t _mb = sb + _b * 8;                                             \
        asm volatile("mbarrier.arrive.expect_tx.shared.b64 _, [%0], %1;"              \
                     :: "r"(_mb), "r"((uint32_t)STAGE_BYTES) : "memory");             \
        bulkcp(sb + 1024 + _b * STAGE_BYTES,         tA + (size_t)(ST) * 8192,        \
               16384u, _mb);                                                          \
        bulkcp(sb + 1024 + _b * STAGE_BYTES + 16384, tB + (size_t)(ST) * 8192,        \
               16384u, _mb);                                                          \
    } while (0)

    if (tid == 0) { ISSUE(0); ISSUE(1); }

    float accf[4][4][4];
    #pragma unroll
    for (int i = 0; i < 4; i++)
        #pragma unroll
        for (int j = 0; j < 4; j++)
            #pragma unroll
            for (int k = 0; k < 4; k++) accf[i][j][k] = 0.f;

    #pragma unroll 1
    for (int s = 0; s < NSTG; s++) {
        const int buf = s % SMEM_BUFS;
        mbar_wait(sb + buf * 8, (uint32_t)((s / SMEM_BUFS) & 1));

        const uint32_t aBase = sb + 1024 + buf * STAGE_BYTES;
        const uint32_t bBase = aBase + 16384;

        #pragma unroll
        for (int kk = 0; kk < 4; kk++) {          // four k16 steps within BK=64
            uint32_t afr[4][4];
            uint32_t bfr[4][2];
            const uint32_t tOff = (kk >> 1) * 8192;      // which packed tile
            const int cc = ((kk & 1) << 1) + (lane >> 4);
            #pragma unroll
            for (int mt = 0; mt < 4; mt++) {
                const int row = wm * 64 + mt * 16 + (lane & 15);
                uint32_t addr = aBase + tOff + row * 64 + ((cc ^ ((row >> 1) & 3)) << 4);
                ldsm4(afr[mt][0], afr[mt][1], afr[mt][2], afr[mt][3], addr);
            }
            #pragma unroll
            for (int np = 0; np < 2; np++) {
                const int row = wn * 32 + np * 16 + (lane & 15);
                uint32_t addr = bBase + tOff + row * 64 + ((cc ^ ((row >> 1) & 3)) << 4);
                ldsm4(bfr[2 * np][0], bfr[2 * np + 1][0],
                      bfr[2 * np][1], bfr[2 * np + 1][1], addr);
            }
            #pragma unroll
            for (int mt = 0; mt < 4; mt++)
                #pragma unroll
                for (int nt = 0; nt < 4; nt++)
                    mma_f16(accf[mt][nt], afr[mt], bfr[nt]);
        }
        __syncthreads();
        if (s + 2 < NSTG && tid == 0) ISSUE(s + 2);
    }
#undef ISSUE

    // ---- epilogue: + agent/goal gathers + bias, sigmoid, store half2(r,p) --
    #pragma unroll
    for (int mt = 0; mt < 4; mt++) {
        #pragma unroll
        for (int rsub = 0; rsub < 2; rsub++) {
            const int gr = bm + wm * 64 + mt * 16 + (lane >> 2) + rsub * 8;
            const int ai = d_agent[gr];
            const int gi = d_goal[gr];
            const float av = d_aval[gr];
            const float gv = d_gval[gr];
            const float* arow = Phi_w + (size_t)(3 * ai + 1) * NOUT;
            const float* grow = Phi_w + (size_t)(3 * gi + 2) * NOUT;
            #pragma unroll
            for (int nt = 0; nt < 4; nt++) {
                const int gn = bn + wn * 32 + nt * 8 + (lane & 3) * 2;
                float x0 = accf[mt][nt][rsub * 2 + 0]
                         + av * arow[gn] + gv * grow[gn] + Phi_b[gn];
                float x1 = accf[mt][nt][rsub * 2 + 1]
                         + av * arow[gn + 1] + gv * grow[gn + 1] + Phi_b[gn + 1];
                float r = 1.f / (1.f + __expf(-x0));
                float p = 1.f / (1.f + __expf(-x1));
                d_phi[(size_t)gr * S + (gn >> 1)] = __floats2half2_rn(r, p);
            }
        }
    }
}

// ---- kernel 3: vprop fp16x2, TWO samples per warp (lo/hi) + MLP head ------
__global__ __launch_bounds__(128) void vprop_kernel(
    const float* __restrict__ obs,
    const float* __restrict__ L1w, const float* __restrict__ L1b,
    const float* __restrict__ L2w, const float* __restrict__ L2b,
    float* __restrict__ out)
{
    const int warp = threadIdx.x >> 5;
    const int lane = threadIdx.x & 31;
    const int b0 = (blockIdx.x * 4 + warp) * 2;      // sample in lo half
    const int b1 = b0 + 1;                           // sample in hi half
    const unsigned FULL = 0xFFFFFFFFu;

    __shared__ __half2 Vsh[4][S];                    // 16KB: final V per warp
    __shared__ float ssel[4][36];
    __shared__ float shh[4][16];

    __half2 V[32], p2[32], a2[32];
    const __half2* phi0 = d_phi + (size_t)b0 * S;
    const __half2* phi1 = d_phi + (size_t)b1 * S;
    #pragma unroll
    for (int i = 0; i < 32; i++) {
        uint32_t u0 = *(const uint32_t*)&phi0[i * 32 + lane];   // (r0,p0)
        uint32_t u1 = *(const uint32_t*)&phi1[i * 32 + lane];   // (r1,p1)
        uint32_t Vu = __byte_perm(u0, u1, 0x5410);              // (r0,r1)
        uint32_t Pu = __byte_perm(u0, u1, 0x7632);              // (p0,p1)
        V[i]  = *(__half2*)&Vu;
        p2[i] = *(__half2*)&Pu;
        a2[i] = __hsub2(V[i], __hmul2(V[i], p2[i]));            // r*(1-p)
    }

    // 20 Jacobi iterations; out-of-range shfl returns self -> boundary no-op
    #pragma unroll 1
    for (int it = 0; it < KITER; it++) {
        __half2 prev = V[0];
        #pragma unroll
        for (int i = 0; i < 32; i++) {
            __half2 cur = V[i];
            __half2 dn  = (i < 31) ? V[i + 1] : cur;
            uint32_t cu = *(uint32_t*)&cur;
            uint32_t lfu = __shfl_up_sync(FULL, cu, 1);
            uint32_t rtu = __shfl_down_sync(FULL, cu, 1);
            __half2 lf = *(__half2*)&lfu;
            __half2 rt = *(__half2*)&rtu;
            __half2 nbr = __hmax2(__hmax2(prev, dn), __hmax2(lf, rt));
            V[i] = __hmax2(cur, __hfma2(p2[i], nbr, a2[i]));
            prev = cur;
        }
    }

    #pragma unroll
    for (int i = 0; i < 32; i++)
        Vsh[warp][i * 32 + lane] = V[i];
    __syncwarp();

    // ---- heads: two samples sequentially, whole warp participates ---------
    #pragma unroll 1
    for (int sh = 0; sh < 2; sh++) {
        const int b = b0 + sh;
        const int ai = d_agent[b];
        const int gi = d_goal[b];
        const int pi = ai >> 5, pj = ai & 31;
        if (lane < 9) {
            const int di = lane / 3, dj = lane - di * 3;
            const int ii = pi + di - 1, jj = pj + dj - 1;
            const bool inb = (ii >= 0) && (ii < 32) && (jj >= 0) && (jj < 32);
            const int sp = ii * 32 + jj;
            float vv = 0.f;
            if (inb) {
                __half2 h = Vsh[warp][sp];
                vv = sh ? __high2float(h) : __low2float(h);
            }
            ssel[warp][lane * 4 + 0] = inb ? obs[(size_t)b * DIN + sp * 3 + 0] : 0.f;
            ssel[warp][lane * 4 + 1] = (lane == 4) ? 1.f : 0.f;
            ssel[warp][lane * 4 + 2] = (inb && sp == gi) ? 1.f : 0.f;
            ssel[warp][lane * 4 + 3] = vv;
        }
        __syncwarp();
        if (lane < 16) {
            float h = L1b[lane];
            #pragma unroll
            for (int f = 0; f < 36; f++) h = fmaf(ssel[warp][f], L1w[f * 16 + lane], h);
            shh[warp][lane] = fmaxf(h, 0.f);
        }
        __syncwarp();
        if (lane < 4) {
            float o = L2b[lane];
            #pragma unroll
            for (int k = 0; k < 16; k++) o = fmaf(shh[warp][k], L2w[k * 4 + lane], o);
            out[(size_t)b * 4 + lane] = o;
        }
        __syncwarp();
    }
}

// ---------------------------------------------------------------------------
extern "C" void kernel_launch(void* const* d_in, const int* in_sizes, int n_in,
                              void* d_out, int out_size) {
    const float* obs   = (const float*)d_in[0];
    const float* Phi_w = (const float*)d_in[1];
    const float* Phi_b = (const float*)d_in[2];
    const float* L1w   = (const float*)d_in[3];
    const float* L1b   = (const float*)d_in[4];
    const float* L2w   = (const float*)d_in[5];
    const float* L2b   = (const float*)d_in[6];
    float* out = (float*)d_out;

    prep_fused_kernel<<<Bn + 2048, 256>>>(obs, Phi_w);
    cudaFuncSetAttribute(gemm_kernel,
                         cudaFuncAttributeMaxDynamicSharedMemorySize, GEMM_SMEM);
    dim3 g(NOUT / BN, Bn / BM);
    gemm_kernel<<<g, 256, GEMM_SMEM>>>(Phi_w, Phi_b);
    vprop_kernel<<<Bn / 8, 128>>>(obs, L1w, L1b, L2w, L2b, out);
}